// round 6
// baseline (speedup 1.0000x reference)
#include <cuda_runtime.h>
#include <cstdint>

#define NN 100000
#define NE 800000
#define HH 128

// ---------------- scratch (device globals; no allocations allowed) ----------
__device__ int   g_deg_out[NN];
__device__ int   g_deg_in [NN];
__device__ int   g_off_out[NN + 1];
__device__ int   g_off_in [NN + 1];
__device__ int   g_cur_out[NN];
__device__ int   g_cur_in [NN];
__device__ int   g_nbr_fwd[NE];   // for node i: list of dst(j) over edges (i,j)
__device__ int   g_nbr_bwd[NE];   // for node j: list of src(i) over edges (i,j)
__device__ float g_S_fwd[(size_t)NN * HH];
__device__ float g_S_bwd[(size_t)NN * HH];

// ---------------- helpers ----------------------------------------------------
__device__ __forceinline__ unsigned long long pack2(float x, float y) {
    unsigned long long r;
    asm("mov.b64 %0, {%1, %2};" : "=l"(r) : "f"(x), "f"(y));
    return r;
}
__device__ __forceinline__ void unpack2(unsigned long long v, float& lo, float& hi) {
    asm("mov.b64 {%0, %1}, %2;" : "=f"(lo), "=f"(hi) : "l"(v));
}
__device__ __forceinline__ void ffma2(unsigned long long& c,
                                      unsigned long long a,
                                      unsigned long long b) {
    asm("fma.rn.f32x2 %0, %1, %2, %0;" : "+l"(c) : "l"(a), "l"(b));
}

// ---------------- K0: zero degree counters -----------------------------------
__global__ void zero_deg_kernel() {
    int i = blockIdx.x * blockDim.x + threadIdx.x;
    if (i < NN) { g_deg_out[i] = 0; g_deg_in[i] = 0; }
}

// ---------------- K1: degree histogram ---------------------------------------
__global__ void hist_kernel(const int* __restrict__ src, const int* __restrict__ dst) {
    int e = blockIdx.x * blockDim.x + threadIdx.x;
    if (e < NE) {
        atomicAdd(&g_deg_out[src[e]], 1);
        atomicAdd(&g_deg_in [dst[e]], 1);
    }
}

// ---------------- K2: exclusive scan (2 blocks, shuffle-based) ---------------
__global__ void scan_kernel() {
    const int* deg = (blockIdx.x == 0) ? g_deg_out : g_deg_in;
    int*       off = (blockIdx.x == 0) ? g_off_out : g_off_in;
    int*       cur = (blockIdx.x == 0) ? g_cur_out : g_cur_in;

    __shared__ int warp_sums[32];
    __shared__ int s_carry;
    int t = threadIdx.x, lane = t & 31, wid = t >> 5;
    if (t == 0) s_carry = 0;
    __syncthreads();

    for (int base = 0; base < NN; base += 1024) {
        int v = (base + t < NN) ? deg[base + t] : 0;
        // warp inclusive scan
        int x = v;
        #pragma unroll
        for (int o = 1; o < 32; o <<= 1) {
            int y = __shfl_up_sync(0xffffffffu, x, o);
            if (lane >= o) x += y;
        }
        if (lane == 31) warp_sums[wid] = x;
        __syncthreads();
        if (wid == 0) {
            int w = warp_sums[lane];
            #pragma unroll
            for (int o = 1; o < 32; o <<= 1) {
                int y = __shfl_up_sync(0xffffffffu, w, o);
                if (lane >= o) w += y;
            }
            warp_sums[lane] = w;
        }
        __syncthreads();
        int incl = x + (wid > 0 ? warp_sums[wid - 1] : 0);
        int carry = s_carry;
        if (base + t < NN) {
            int excl = carry + incl - v;
            off[base + t] = excl;
            cur[base + t] = excl;
        }
        __syncthreads();                 // everyone has read s_carry / warp_sums
        if (t == 1023) s_carry = carry + incl;   // block total
        __syncthreads();
    }
    if (t == 0) off[NN] = s_carry;
}

// ---------------- K3: scatter edge endpoints into CSR lists ------------------
__global__ void build_kernel(const int* __restrict__ src, const int* __restrict__ dst) {
    int e = blockIdx.x * blockDim.x + threadIdx.x;
    if (e < NE) {
        int s = src[e], d = dst[e];
        int p = atomicAdd(&g_cur_out[s], 1);
        g_nbr_fwd[p] = d;
        int q = atomicAdd(&g_cur_in[d], 1);
        g_nbr_bwd[q] = s;
    }
}

// ---------------- K4: gather aggregation (one warp per node) -----------------
__global__ void agg_kernel(const float* __restrict__ h) {
    int warp = (blockIdx.x * blockDim.x + threadIdx.x) >> 5;
    if (warp >= NN) return;
    int lane = threadIdx.x & 31;

    float4 af = make_float4(0.f, 0.f, 0.f, 0.f);
    float4 ab = make_float4(0.f, 0.f, 0.f, 0.f);

    int b0 = g_off_out[warp], e0 = g_off_out[warp + 1];
    for (int k = b0; k < e0; k++) {
        int j = g_nbr_fwd[k];
        float4 v = __ldg((const float4*)(h + (size_t)j * HH) + lane);
        af.x += v.x; af.y += v.y; af.z += v.z; af.w += v.w;
    }
    int b1 = g_off_in[warp], e1 = g_off_in[warp + 1];
    for (int k = b1; k < e1; k++) {
        int j = g_nbr_bwd[k];
        float4 v = __ldg((const float4*)(h + (size_t)j * HH) + lane);
        ab.x += v.x; ab.y += v.y; ab.z += v.z; ab.w += v.w;
    }
    ((float4*)(g_S_fwd + (size_t)warp * HH))[lane] = af;
    ((float4*)(g_S_bwd + (size_t)warp * HH))[lane] = ab;
}

// ---------------- K5: fused GEMM (K = 3*128) + degree-biases + relu ----------
// out[i,n] = relu(  h[i,:]·Ws_w[n,:] + S_fwd[i,:]·W_w[n,:] + S_bwd[i,:]·Wt_w[n,:]
//                 + Ws_b[n] + deg_out[i]*W_b[n] + deg_in[i]*Wt_b[n] )
__global__ __launch_bounds__(256, 2)
void gemm_kernel(const float* __restrict__ h,
                 const float* __restrict__ Ww,  const float* __restrict__ Wb,
                 const float* __restrict__ Wsw, const float* __restrict__ Wsb,
                 const float* __restrict__ Wtw, const float* __restrict__ Wtb,
                 float* __restrict__ out) {
    __shared__ float As[8][132];   // As[k][m], padded rows: conflict-free LDS.128
    __shared__ float Bs[8][132];   // Bs[k][n] = W[n][k]

    const int tid = threadIdx.x;
    const int m0  = blockIdx.x * 128;
    const int tx  = tid & 15;        // output-col group (8 cols each)
    const int ty  = tid >> 4;        // output-row group (8 rows each)
    const int lrow = tid >> 1;       // 0..127 : tile row/col for loads
    const int lk4  = (tid & 1) * 4;  // 0 or 4 : k sub-offset

    unsigned long long c[8][4];      // 8 rows x 4 packed col-pairs (fp32x2)
    #pragma unroll
    for (int i = 0; i < 8; i++)
        #pragma unroll
        for (int j = 0; j < 4; j++) c[i][j] = 0ull;   // bits(0,0) == (0.f,0.f)

    const float* Aseg[3] = { h, g_S_fwd, g_S_bwd };
    const float* Wseg[3] = { Wsw, Ww, Wtw };

    for (int s = 0; s < 3; s++) {
        const float* A = Aseg[s];
        const float* W = Wseg[s];
        for (int kb = 0; kb < HH; kb += 8) {
            // --- load A tile (128 rows x 8 k), transposed into smem ---
            int arow = m0 + lrow;
            float4 av = make_float4(0.f, 0.f, 0.f, 0.f);
            if (arow < NN)
                av = __ldg((const float4*)(A + (size_t)arow * HH + kb + lk4));
            As[lk4 + 0][lrow] = av.x;
            As[lk4 + 1][lrow] = av.y;
            As[lk4 + 2][lrow] = av.z;
            As[lk4 + 3][lrow] = av.w;
            // --- load B tile: Bs[k][n] = W[n][kb+k] ---
            float4 bv = __ldg((const float4*)(W + (size_t)lrow * HH + kb + lk4));
            Bs[lk4 + 0][lrow] = bv.x;
            Bs[lk4 + 1][lrow] = bv.y;
            Bs[lk4 + 2][lrow] = bv.z;
            Bs[lk4 + 3][lrow] = bv.w;
            __syncthreads();

            #pragma unroll
            for (int kk = 0; kk < 8; kk++) {
                float4 a0 = *(const float4*)&As[kk][ty * 8];
                float4 a1 = *(const float4*)&As[kk][ty * 8 + 4];
                float4 b0 = *(const float4*)&Bs[kk][tx * 8];
                float4 b1 = *(const float4*)&Bs[kk][tx * 8 + 4];
                unsigned long long bp[4];
                bp[0] = pack2(b0.x, b0.y);
                bp[1] = pack2(b0.z, b0.w);
                bp[2] = pack2(b1.x, b1.y);
                bp[3] = pack2(b1.z, b1.w);
                float aa[8] = { a0.x, a0.y, a0.z, a0.w, a1.x, a1.y, a1.z, a1.w };
                #pragma unroll
                for (int i = 0; i < 8; i++) {
                    unsigned long long ap = pack2(aa[i], aa[i]);
                    #pragma unroll
                    for (int j = 0; j < 4; j++) ffma2(c[i][j], ap, bp[j]);
                }
            }
            __syncthreads();
        }
    }

    // --- epilogue: biases (with degree scaling) + relu ---
    const int ncol = tx * 8;
    float vsb[8], vwb[8], vtb[8];
    #pragma unroll
    for (int j = 0; j < 8; j++) {
        vsb[j] = __ldg(Wsb + ncol + j);
        vwb[j] = __ldg(Wb  + ncol + j);
        vtb[j] = __ldg(Wtb + ncol + j);
    }
    #pragma unroll
    for (int i = 0; i < 8; i++) {
        int row = m0 + ty * 8 + i;
        if (row >= NN) continue;
        float dO = (float)g_deg_out[row];
        float dI = (float)g_deg_in[row];
        float v[8];
        #pragma unroll
        for (int j = 0; j < 4; j++) unpack2(c[i][j], v[2 * j], v[2 * j + 1]);
        #pragma unroll
        for (int j = 0; j < 8; j++) {
            float r = v[j] + vsb[j] + dO * vwb[j] + dI * vtb[j];
            v[j] = r > 0.f ? r : 0.f;
        }
        float* o = out + (size_t)row * HH + ncol;
        *(float4*)(o + 0) = make_float4(v[0], v[1], v[2], v[3]);
        *(float4*)(o + 4) = make_float4(v[4], v[5], v[6], v[7]);
    }
}

// ---------------- launcher ----------------------------------------------------
extern "C" void kernel_launch(void* const* d_in, const int* in_sizes, int n_in,
                              void* d_out, int out_size) {
    const float* h_n  = (const float*)d_in[0];
    const int*   esrc = (const int*)  d_in[1];
    const int*   edst = (const int*)  d_in[2];
    const float* W_w  = (const float*)d_in[3];
    const float* W_b  = (const float*)d_in[4];
    const float* Ws_w = (const float*)d_in[5];
    const float* Ws_b = (const float*)d_in[6];
    const float* Wt_w = (const float*)d_in[7];
    const float* Wt_b = (const float*)d_in[8];
    float* out = (float*)d_out;

    zero_deg_kernel<<<(NN + 255) / 256, 256>>>();
    hist_kernel<<<(NE + 255) / 256, 256>>>(esrc, edst);
    scan_kernel<<<2, 1024>>>();
    build_kernel<<<(NE + 255) / 256, 256>>>(esrc, edst);
    agg_kernel<<<(NN * 32 + 255) / 256, 256>>>(h_n);
    gemm_kernel<<<(NN + 127) / 128, 256>>>(h_n, W_w, W_b, Ws_w, Ws_b, Wt_w, Wt_b, out);
}

// round 12
// speedup vs baseline: 1.9497x; 1.9497x over previous
#include <cuda_runtime.h>
#include <cuda_bf16.h>
#include <cstdint>

#define NN 100000
#define NE 800000
#define HH 128

// ---------------- scratch (device globals; no allocations allowed) ----------
__device__ int   g_deg_out[NN];
__device__ int   g_deg_in [NN];
__device__ int   g_off_out[NN + 1];
__device__ int   g_off_in [NN + 1];
__device__ int   g_cur_out[NN];
__device__ int   g_cur_in [NN];
__device__ int   g_nbr_fwd[NE];   // for node i: list of dst(j) over edges (i,j)
__device__ int   g_nbr_bwd[NE];   // for node j: list of src(i) over edges (i,j)
__device__ float g_S_fwd[(size_t)NN * HH];
__device__ float g_S_bwd[(size_t)NN * HH];
// concatenated weight matrix [N=128][K=384], split into bf16 hi/lo.
// k-layout: seg0 = Ws_w (vs h), seg1 = W_w (vs S_fwd), seg2 = Wt_w (vs S_bwd)
__device__ __align__(16) __nv_bfloat16 g_B_hi[128 * 384];
__device__ __align__(16) __nv_bfloat16 g_B_lo[128 * 384];

// ---------------- K0: zero degree counters -----------------------------------
__global__ void zero_deg_kernel() {
    int i = blockIdx.x * blockDim.x + threadIdx.x;
    if (i < NN) { g_deg_out[i] = 0; g_deg_in[i] = 0; }
}

// ---------------- K1: degree histogram ---------------------------------------
__global__ void hist_kernel(const int* __restrict__ src, const int* __restrict__ dst) {
    int e = blockIdx.x * blockDim.x + threadIdx.x;
    if (e < NE) {
        atomicAdd(&g_deg_out[src[e]], 1);
        atomicAdd(&g_deg_in [dst[e]], 1);
    }
}

// ---------------- K2: exclusive scan (2 blocks, shuffle-based) ---------------
__global__ void scan_kernel() {
    const int* deg = (blockIdx.x == 0) ? g_deg_out : g_deg_in;
    int*       off = (blockIdx.x == 0) ? g_off_out : g_off_in;
    int*       cur = (blockIdx.x == 0) ? g_cur_out : g_cur_in;

    __shared__ int warp_sums[32];
    __shared__ int s_carry;
    int t = threadIdx.x, lane = t & 31, wid = t >> 5;
    if (t == 0) s_carry = 0;
    __syncthreads();

    for (int base = 0; base < NN; base += 1024) {
        int v = (base + t < NN) ? deg[base + t] : 0;
        int x = v;
        #pragma unroll
        for (int o = 1; o < 32; o <<= 1) {
            int y = __shfl_up_sync(0xffffffffu, x, o);
            if (lane >= o) x += y;
        }
        if (lane == 31) warp_sums[wid] = x;
        __syncthreads();
        if (wid == 0) {
            int w = warp_sums[lane];
            #pragma unroll
            for (int o = 1; o < 32; o <<= 1) {
                int y = __shfl_up_sync(0xffffffffu, w, o);
                if (lane >= o) w += y;
            }
            warp_sums[lane] = w;
        }
        __syncthreads();
        int incl = x + (wid > 0 ? warp_sums[wid - 1] : 0);
        int carry = s_carry;
        if (base + t < NN) {
            int excl = carry + incl - v;
            off[base + t] = excl;
            cur[base + t] = excl;
        }
        __syncthreads();
        if (t == 1023) s_carry = carry + incl;
        __syncthreads();
    }
    if (t == 0) off[NN] = s_carry;
}

// ---------------- K3: scatter edge endpoints into CSR lists ------------------
__global__ void build_kernel(const int* __restrict__ src, const int* __restrict__ dst) {
    int e = blockIdx.x * blockDim.x + threadIdx.x;
    if (e < NE) {
        int s = src[e], d = dst[e];
        int p = atomicAdd(&g_cur_out[s], 1);
        g_nbr_fwd[p] = d;
        int q = atomicAdd(&g_cur_in[d], 1);
        g_nbr_bwd[q] = s;
    }
}

// ---------------- K4: gather aggregation (one warp per node) -----------------
__global__ void agg_kernel(const float* __restrict__ h) {
    int warp = (blockIdx.x * blockDim.x + threadIdx.x) >> 5;
    if (warp >= NN) return;
    int lane = threadIdx.x & 31;

    float4 af = make_float4(0.f, 0.f, 0.f, 0.f);
    float4 ab = make_float4(0.f, 0.f, 0.f, 0.f);

    int b0 = g_off_out[warp], e0 = g_off_out[warp + 1];
    for (int k = b0; k < e0; k++) {
        int j = g_nbr_fwd[k];
        float4 v = __ldg((const float4*)(h + (size_t)j * HH) + lane);
        af.x += v.x; af.y += v.y; af.z += v.z; af.w += v.w;
    }
    int b1 = g_off_in[warp], e1 = g_off_in[warp + 1];
    for (int k = b1; k < e1; k++) {
        int j = g_nbr_bwd[k];
        float4 v = __ldg((const float4*)(h + (size_t)j * HH) + lane);
        ab.x += v.x; ab.y += v.y; ab.z += v.z; ab.w += v.w;
    }
    ((float4*)(g_S_fwd + (size_t)warp * HH))[lane] = af;
    ((float4*)(g_S_bwd + (size_t)warp * HH))[lane] = ab;
}

// ---------------- K5a: split weights into bf16 hi/lo concatenated B ----------
__global__ void prep_b_kernel(const float* __restrict__ Ww,
                              const float* __restrict__ Wsw,
                              const float* __restrict__ Wtw) {
    int i = blockIdx.x * blockDim.x + threadIdx.x;   // over 128*384
    if (i >= 128 * 384) return;
    int n  = i / 384;
    int k  = i % 384;
    int s  = k >> 7;        // 0:Ws_w  1:W_w  2:Wt_w
    int kk = k & 127;
    const float* W = (s == 0) ? Wsw : (s == 1) ? Ww : Wtw;
    float x = W[n * 128 + kk];
    __nv_bfloat16 hi = __float2bfloat16_rn(x);
    float r = x - __bfloat162float(hi);
    g_B_hi[i] = hi;
    g_B_lo[i] = __float2bfloat16_rn(r);
}

// ---------------- K5b: mma.sync bf16 split GEMM, K=384, fused epilogue -------
// out[i,n] = relu( [h|S_fwd|S_bwd][i,:] . Bcat[n,:]
//                  + Ws_b[n] + deg_out[i]*W_b[n] + deg_in[i]*Wt_b[n] )
//
// smem tiles: bf16 [128 rows][64 k] with 72-element (144 B) row stride
// -> fragment LDS patterns are bank-conflict-free (rows 4 banks apart,
//    4-lane k-groups contiguous: covers all 32 banks).
#define ROWB 144                       // bytes per smem row (72 bf16)
#define SA_HI 0
#define SA_LO (SA_HI + 128 * ROWB)
#define SB_HI (SA_LO + 128 * ROWB)
#define SB_LO (SB_HI + 128 * ROWB)
#define SM_TOT (SB_LO + 128 * ROWB)    // 73728 bytes

__device__ __forceinline__ void mma_bf16(float* d, const uint32_t* a,
                                         const uint32_t* b) {
    asm volatile(
        "mma.sync.aligned.m16n8k16.row.col.f32.bf16.bf16.f32 "
        "{%0,%1,%2,%3}, {%4,%5,%6,%7}, {%8,%9}, {%0,%1,%2,%3};"
        : "+f"(d[0]), "+f"(d[1]), "+f"(d[2]), "+f"(d[3])
        : "r"(a[0]), "r"(a[1]), "r"(a[2]), "r"(a[3]), "r"(b[0]), "r"(b[1]));
}

__global__ __launch_bounds__(256)
void gemm_mma_kernel(const float* __restrict__ h,
                     const float* __restrict__ Wb,
                     const float* __restrict__ Wsb,
                     const float* __restrict__ Wtb,
                     float* __restrict__ out) {
    extern __shared__ __align__(16) char smem[];

    const int tid = threadIdx.x;
    const int wid = tid >> 5;
    const int lid = tid & 31;
    const int g   = lid >> 2;        // mma group id (0..7)
    const int tg  = lid & 3;         // thread-in-group (0..3)
    const int m0  = blockIdx.x * 128;
    const int wm  = wid & 3;         // warp m-tile (4 x 32 rows)
    const int wn  = wid >> 2;        // warp n-tile (2 x 64 cols)

    // accumulators: 2 m16 tiles x 8 n8 tiles x 4 fp32
    float acc[2][8][4];
    #pragma unroll
    for (int i = 0; i < 2; i++)
        #pragma unroll
        for (int j = 0; j < 8; j++)
            #pragma unroll
            for (int q = 0; q < 4; q++) acc[i][j][q] = 0.f;

    // A load/convert assignment: 2 threads per row, 32 floats each
    const int arow  = tid >> 1;      // 0..127
    const int ahalf = tid & 1;
    int row_g = m0 + arow;
    if (row_g >= NN) row_g = NN - 1; // clamp; garbage rows never stored

    for (int c = 0; c < 6; c++) {
        const int seg  = c >> 1;
        const int koff = (c & 1) * 64;
        const float* A = (seg == 0) ? h : (seg == 1) ? g_S_fwd : g_S_bwd;
        const float* ap = A + (size_t)row_g * HH + koff + ahalf * 32;

        // ---- A chunk: fp32 -> bf16 hi/lo into smem ----
        #pragma unroll
        for (int q = 0; q < 4; q++) {
            float4 f0 = __ldg((const float4*)(ap + q * 8));
            float4 f1 = __ldg((const float4*)(ap + q * 8) + 1);
            float xs[8] = { f0.x, f0.y, f0.z, f0.w, f1.x, f1.y, f1.z, f1.w };
            uint32_t hi[4], lo[4];
            #pragma unroll
            for (int p = 0; p < 4; p++) {
                float a0 = xs[2 * p], a1 = xs[2 * p + 1];
                __nv_bfloat162 hh = __floats2bfloat162_rn(a0, a1);
                hi[p] = *(uint32_t*)&hh;
                float r0 = a0 - __bfloat162float(__low2bfloat16(hh));
                float r1 = a1 - __bfloat162float(__high2bfloat16(hh));
                __nv_bfloat162 ll = __floats2bfloat162_rn(r0, r1);
                lo[p] = *(uint32_t*)&ll;
            }
            int off = arow * ROWB + (ahalf * 32 + q * 8) * 2;
            *(uint4*)(smem + SA_HI + off) = make_uint4(hi[0], hi[1], hi[2], hi[3]);
            *(uint4*)(smem + SA_LO + off) = make_uint4(lo[0], lo[1], lo[2], lo[3]);
        }

        // ---- B chunk: bf16 [n][k] rows of 64 k (128 B), 2 threads per n ----
        {
            int bn = tid >> 1, bh = tid & 1;
            size_t gofs = (size_t)bn * 768 + (size_t)c * 128 + (size_t)bh * 64;
            int soff = bn * ROWB + bh * 64;
            #pragma unroll
            for (int q = 0; q < 4; q++) {
                uint4 vh = __ldg((const uint4*)((const char*)g_B_hi + gofs + q * 16));
                uint4 vl = __ldg((const uint4*)((const char*)g_B_lo + gofs + q * 16));
                *(uint4*)(smem + SB_HI + soff + q * 16) = vh;
                *(uint4*)(smem + SB_LO + soff + q * 16) = vl;
            }
        }
        __syncthreads();

        // ---- compute: 4 k16 steps ----
        #pragma unroll
        for (int ks = 0; ks < 4; ks++) {
            const int kb = (ks * 16 + tg * 2) * 2;     // byte offset of k pair
            uint32_t ahi[2][4], alo[2][4];
            #pragma unroll
            for (int mt = 0; mt < 2; mt++) {
                int r = (wm * 32 + mt * 16 + g) * ROWB + kb;
                ahi[mt][0] = *(const uint32_t*)(smem + SA_HI + r);
                ahi[mt][1] = *(const uint32_t*)(smem + SA_HI + r + 8 * ROWB);
                ahi[mt][2] = *(const uint32_t*)(smem + SA_HI + r + 16);
                ahi[mt][3] = *(const uint32_t*)(smem + SA_HI + r + 8 * ROWB + 16);
                alo[mt][0] = *(const uint32_t*)(smem + SA_LO + r);
                alo[mt][1] = *(const uint32_t*)(smem + SA_LO + r + 8 * ROWB);
                alo[mt][2] = *(const uint32_t*)(smem + SA_LO + r + 16);
                alo[mt][3] = *(const uint32_t*)(smem + SA_LO + r + 8 * ROWB + 16);
            }
            #pragma unroll
            for (int nt = 0; nt < 8; nt++) {
                int bofs = (wn * 64 + nt * 8 + g) * ROWB + kb;
                uint32_t bhi[2], blo[2];
                bhi[0] = *(const uint32_t*)(smem + SB_HI + bofs);
                bhi[1] = *(const uint32_t*)(smem + SB_HI + bofs + 16);
                blo[0] = *(const uint32_t*)(smem + SB_LO + bofs);
                blo[1] = *(const uint32_t*)(smem + SB_LO + bofs + 16);
                #pragma unroll
                for (int mt = 0; mt < 2; mt++) {
                    mma_bf16(acc[mt][nt], ahi[mt], bhi);
                    mma_bf16(acc[mt][nt], ahi[mt], blo);
                    mma_bf16(acc[mt][nt], alo[mt], bhi);
                }
            }
        }
        __syncthreads();   // single-buffered: protect smem before next fill
    }

    // ---- epilogue: degree-scaled biases + relu ----
    #pragma unroll
    for (int mt = 0; mt < 2; mt++) {
        int r0 = m0 + wm * 32 + mt * 16 + g;
        int r1 = r0 + 8;
        float dO0 = 0.f, dI0 = 0.f, dO1 = 0.f, dI1 = 0.f;
        if (r0 < NN) { dO0 = (float)g_deg_out[r0]; dI0 = (float)g_deg_in[r0]; }
        if (r1 < NN) { dO1 = (float)g_deg_out[r1]; dI1 = (float)g_deg_in[r1]; }
        #pragma unroll
        for (int nt = 0; nt < 8; nt++) {
            int ncol = wn * 64 + nt * 8 + tg * 2;
            float2 sbv = __ldg((const float2*)(Wsb + ncol));
            float2 wbv = __ldg((const float2*)(Wb  + ncol));
            float2 tbv = __ldg((const float2*)(Wtb + ncol));
            if (r0 < NN) {
                float v0 = acc[mt][nt][0] + sbv.x + dO0 * wbv.x + dI0 * tbv.x;
                float v1 = acc[mt][nt][1] + sbv.y + dO0 * wbv.y + dI0 * tbv.y;
                v0 = v0 > 0.f ? v0 : 0.f;
                v1 = v1 > 0.f ? v1 : 0.f;
                *(float2*)(out + (size_t)r0 * HH + ncol) = make_float2(v0, v1);
            }
            if (r1 < NN) {
                float v2 = acc[mt][nt][2] + sbv.x + dO1 * wbv.x + dI1 * tbv.x;
                float v3 = acc[mt][nt][3] + sbv.y + dO1 * wbv.y + dI1 * tbv.y;
                v2 = v2 > 0.f ? v2 : 0.f;
                v3 = v3 > 0.f ? v3 : 0.f;
                *(float2*)(out + (size_t)r1 * HH + ncol) = make_float2(v2, v3);
            }
        }
    }
}

// ---------------- launcher ----------------------------------------------------
extern "C" void kernel_launch(void* const* d_in, const int* in_sizes, int n_in,
                              void* d_out, int out_size) {
    const float* h_n  = (const float*)d_in[0];
    const int*   esrc = (const int*)  d_in[1];
    const int*   edst = (const int*)  d_in[2];
    const float* W_w  = (const float*)d_in[3];
    const float* W_b  = (const float*)d_in[4];
    const float* Ws_w = (const float*)d_in[5];
    const float* Ws_b = (const float*)d_in[6];
    const float* Wt_w = (const float*)d_in[7];
    const float* Wt_b = (const float*)d_in[8];
    float* out = (float*)d_out;

    cudaFuncSetAttribute(gemm_mma_kernel,
                         cudaFuncAttributeMaxDynamicSharedMemorySize, SM_TOT);

    prep_b_kernel<<<(128 * 384 + 255) / 256, 256>>>(W_w, Ws_w, Wt_w);
    zero_deg_kernel<<<(NN + 255) / 256, 256>>>();
    hist_kernel<<<(NE + 255) / 256, 256>>>(esrc, edst);
    scan_kernel<<<2, 1024>>>();
    build_kernel<<<(NE + 255) / 256, 256>>>(esrc, edst);
    agg_kernel<<<(NN * 32 + 255) / 256, 256>>>(h_n);
    gemm_mma_kernel<<<(NN + 127) / 128, 256, SM_TOT>>>(h_n, W_b, Ws_b, Wt_b, out);
}

// round 15
// speedup vs baseline: 2.4082x; 1.2351x over previous
#include <cuda_runtime.h>
#include <cuda_bf16.h>
#include <cstdint>

#define NN 100000
#define NE 800000
#define HH 128
#define SCAN_BLKS 98            // ceil(100000 / 1024)

// ---------------- scratch (device globals; no allocations allowed) ----------
__device__ int   g_deg_out[NN];
__device__ int   g_deg_in [NN];
__device__ int   g_off_out[NN + 1];
__device__ int   g_off_in [NN + 1];
__device__ int   g_cur_out[NN];
__device__ int   g_cur_in [NN];
__device__ int   g_nbr_fwd[NE];   // for node i: list of dst(j) over edges (i,j)
__device__ int   g_nbr_bwd[NE];   // for node j: list of src(i) over edges (i,j)
__device__ int   g_bsum[2][128];  // per-block partial sums for the 2 scans
__device__ float g_S_fwd[(size_t)NN * HH];
__device__ float g_S_bwd[(size_t)NN * HH];
// concatenated weight matrix [N=128][K=384], split into bf16 hi/lo.
// k-layout: seg0 = Ws_w (vs h), seg1 = W_w (vs S_fwd), seg2 = Wt_w (vs S_bwd)
__device__ __align__(16) __nv_bfloat16 g_B_hi[128 * 384];
__device__ __align__(16) __nv_bfloat16 g_B_lo[128 * 384];

// ---------------- K0: zero degree counters -----------------------------------
__global__ void zero_deg_kernel() {
    int i = blockIdx.x * blockDim.x + threadIdx.x;
    if (i < NN) { g_deg_out[i] = 0; g_deg_in[i] = 0; }
}

// ---------------- K1: degree histogram ---------------------------------------
__global__ void hist_kernel(const int* __restrict__ src, const int* __restrict__ dst) {
    int e = blockIdx.x * blockDim.x + threadIdx.x;
    if (e < NE) {
        atomicAdd(&g_deg_out[src[e]], 1);
        atomicAdd(&g_deg_in [dst[e]], 1);
    }
}

// ---------------- K2: parallel exclusive scan (3 launches) -------------------
// scan1: per-block exclusive scan + block totals
__global__ void scan1_kernel() {
    const int arr = blockIdx.y;
    const int* deg = arr ? g_deg_in : g_deg_out;
    int*       off = arr ? g_off_in : g_off_out;

    __shared__ int warp_sums[32];
    int t = threadIdx.x, lane = t & 31, wid = t >> 5;
    int idx = blockIdx.x * 1024 + t;

    int v = (idx < NN) ? deg[idx] : 0;
    int x = v;
    #pragma unroll
    for (int o = 1; o < 32; o <<= 1) {
        int y = __shfl_up_sync(0xffffffffu, x, o);
        if (lane >= o) x += y;
    }
    if (lane == 31) warp_sums[wid] = x;
    __syncthreads();
    if (wid == 0) {
        int w = warp_sums[lane];
        #pragma unroll
        for (int o = 1; o < 32; o <<= 1) {
            int y = __shfl_up_sync(0xffffffffu, w, o);
            if (lane >= o) w += y;
        }
        warp_sums[lane] = w;
    }
    __syncthreads();
    int incl = x + (wid > 0 ? warp_sums[wid - 1] : 0);
    if (idx < NN) off[idx] = incl - v;             // local exclusive
    if (t == 1023) g_bsum[arr][blockIdx.x] = incl; // block total
}

// scan2: scan the 98 block totals (one block per array)
__global__ void scan2_kernel() {
    const int arr = blockIdx.x;
    __shared__ int s[128];
    int t = threadIdx.x;
    int v = (t < SCAN_BLKS) ? g_bsum[arr][t] : 0;
    s[t] = v;
    __syncthreads();
    int x = v;
    #pragma unroll
    for (int o = 1; o < 128; o <<= 1) {
        int y = (t >= o) ? s[t - o] : 0;
        __syncthreads();
        x += y;
        s[t] = x;
        __syncthreads();
    }
    g_bsum[arr][t] = x - v;                         // exclusive
    if (t == 127) {
        int* off = arr ? g_off_in : g_off_out;
        off[NN] = x;                                // grand total
    }
}

// scan3: add block offsets, mirror into cursors
__global__ void scan3_kernel() {
    const int arr = blockIdx.y;
    int* off = arr ? g_off_in : g_off_out;
    int* cur = arr ? g_cur_in : g_cur_out;
    int idx = blockIdx.x * 1024 + threadIdx.x;
    if (idx < NN) {
        int o = off[idx] + g_bsum[arr][blockIdx.x];
        off[idx] = o;
        cur[idx] = o;
    }
}

// ---------------- K3: scatter edge endpoints into CSR lists ------------------
__global__ void build_kernel(const int* __restrict__ src, const int* __restrict__ dst) {
    int e = blockIdx.x * blockDim.x + threadIdx.x;
    if (e < NE) {
        int s = src[e], d = dst[e];
        int p = atomicAdd(&g_cur_out[s], 1);
        g_nbr_fwd[p] = d;
        int q = atomicAdd(&g_cur_in[d], 1);
        g_nbr_bwd[q] = s;
    }
}

// ---------------- K4: gather aggregation (one warp per node) -----------------
__global__ void agg_kernel(const float* __restrict__ h) {
    int warp = (blockIdx.x * blockDim.x + threadIdx.x) >> 5;
    if (warp >= NN) return;
    int lane = threadIdx.x & 31;

    float4 af = make_float4(0.f, 0.f, 0.f, 0.f);
    float4 ab = make_float4(0.f, 0.f, 0.f, 0.f);

    int b0 = g_off_out[warp], e0 = g_off_out[warp + 1];
    for (int k = b0; k < e0; k++) {
        int j = g_nbr_fwd[k];
        float4 v = __ldg((const float4*)(h + (size_t)j * HH) + lane);
        af.x += v.x; af.y += v.y; af.z += v.z; af.w += v.w;
    }
    int b1 = g_off_in[warp], e1 = g_off_in[warp + 1];
    for (int k = b1; k < e1; k++) {
        int j = g_nbr_bwd[k];
        float4 v = __ldg((const float4*)(h + (size_t)j * HH) + lane);
        ab.x += v.x; ab.y += v.y; ab.z += v.z; ab.w += v.w;
    }
    ((float4*)(g_S_fwd + (size_t)warp * HH))[lane] = af;
    ((float4*)(g_S_bwd + (size_t)warp * HH))[lane] = ab;
}

// ---------------- K5a: split weights into bf16 hi/lo concatenated B ----------
__global__ void prep_b_kernel(const float* __restrict__ Ww,
                              const float* __restrict__ Wsw,
                              const float* __restrict__ Wtw) {
    int i = blockIdx.x * blockDim.x + threadIdx.x;   // over 128*384
    if (i >= 128 * 384) return;
    int n  = i / 384;
    int k  = i % 384;
    int s  = k >> 7;        // 0:Ws_w  1:W_w  2:Wt_w
    int kk = k & 127;
    const float* W = (s == 0) ? Wsw : (s == 1) ? Ww : Wtw;
    float x = W[n * 128 + kk];
    __nv_bfloat16 hi = __float2bfloat16_rn(x);
    float r = x - __bfloat162float(hi);
    g_B_hi[i] = hi;
    g_B_lo[i] = __float2bfloat16_rn(r);
}

// ---------------- K5b: mma.sync bf16 split GEMM, K=384, fused epilogue -------
// out[i,n] = relu( [h|S_fwd|S_bwd][i,:] . Bcat[n,:]
//                  + Ws_b[n] + deg_out[i]*W_b[n] + deg_in[i]*Wt_b[n] )
#define ROWB 144                       // bytes per smem row (72 bf16)
#define SA_HI 0
#define SA_LO (SA_HI + 128 * ROWB)
#define SB_HI (SA_LO + 128 * ROWB)
#define SB_LO (SB_HI + 128 * ROWB)
#define SM_TOT (SB_LO + 128 * ROWB)    // 73728 bytes

__device__ __forceinline__ void mma_bf16(float* d, const uint32_t* a,
                                         const uint32_t* b) {
    asm volatile(
        "mma.sync.aligned.m16n8k16.row.col.f32.bf16.bf16.f32 "
        "{%0,%1,%2,%3}, {%4,%5,%6,%7}, {%8,%9}, {%0,%1,%2,%3};"
        : "+f"(d[0]), "+f"(d[1]), "+f"(d[2]), "+f"(d[3])
        : "r"(a[0]), "r"(a[1]), "r"(a[2]), "r"(a[3]), "r"(b[0]), "r"(b[1]));
}

__global__ __launch_bounds__(256)
void gemm_mma_kernel(const float* __restrict__ h,
                     const float* __restrict__ Wb,
                     const float* __restrict__ Wsb,
                     const float* __restrict__ Wtb,
                     float* __restrict__ out) {
    extern __shared__ __align__(16) char smem[];

    const int tid = threadIdx.x;
    const int wid = tid >> 5;
    const int lid = tid & 31;
    const int g   = lid >> 2;        // mma group id (0..7)
    const int tg  = lid & 3;         // thread-in-group (0..3)
    const int m0  = blockIdx.x * 128;
    const int wm  = wid & 3;         // warp m-tile (4 x 32 rows)
    const int wn  = wid >> 2;        // warp n-tile (2 x 64 cols)

    float acc[2][8][4];
    #pragma unroll
    for (int i = 0; i < 2; i++)
        #pragma unroll
        for (int j = 0; j < 8; j++)
            #pragma unroll
            for (int q = 0; q < 4; q++) acc[i][j][q] = 0.f;

    const int arow  = tid >> 1;      // 0..127
    const int ahalf = tid & 1;
    int row_g = m0 + arow;
    if (row_g >= NN) row_g = NN - 1; // clamp; garbage rows never stored

    for (int c = 0; c < 6; c++) {
        const int seg  = c >> 1;
        const int koff = (c & 1) * 64;
        const float* A = (seg == 0) ? h : (seg == 1) ? g_S_fwd : g_S_bwd;
        const float* ap = A + (size_t)row_g * HH + koff + ahalf * 32;

        // ---- A chunk: fp32 -> bf16 hi/lo into smem ----
        #pragma unroll
        for (int q = 0; q < 4; q++) {
            float4 f0 = __ldg((const float4*)(ap + q * 8));
            float4 f1 = __ldg((const float4*)(ap + q * 8) + 1);
            float xs[8] = { f0.x, f0.y, f0.z, f0.w, f1.x, f1.y, f1.z, f1.w };
            uint32_t hi[4], lo[4];
            #pragma unroll
            for (int p = 0; p < 4; p++) {
                float a0 = xs[2 * p], a1 = xs[2 * p + 1];
                __nv_bfloat162 hh = __floats2bfloat162_rn(a0, a1);
                hi[p] = *(uint32_t*)&hh;
                float r0 = a0 - __bfloat162float(__low2bfloat16(hh));
                float r1 = a1 - __bfloat162float(__high2bfloat16(hh));
                __nv_bfloat162 ll = __floats2bfloat162_rn(r0, r1);
                lo[p] = *(uint32_t*)&ll;
            }
            int off = arow * ROWB + (ahalf * 32 + q * 8) * 2;
            *(uint4*)(smem + SA_HI + off) = make_uint4(hi[0], hi[1], hi[2], hi[3]);
            *(uint4*)(smem + SA_LO + off) = make_uint4(lo[0], lo[1], lo[2], lo[3]);
        }

        // ---- B chunk: bf16 [n][k] rows of 64 k (128 B), 2 threads per n ----
        {
            int bn = tid >> 1, bh = tid & 1;
            size_t gofs = (size_t)bn * 768 + (size_t)c * 128 + (size_t)bh * 64;
            int soff = bn * ROWB + bh * 64;
            #pragma unroll
            for (int q = 0; q < 4; q++) {
                uint4 vh = __ldg((const uint4*)((const char*)g_B_hi + gofs + q * 16));
                uint4 vl = __ldg((const uint4*)((const char*)g_B_lo + gofs + q * 16));
                *(uint4*)(smem + SB_HI + soff + q * 16) = vh;
                *(uint4*)(smem + SB_LO + soff + q * 16) = vl;
            }
        }
        __syncthreads();

        // ---- compute: 4 k16 steps ----
        #pragma unroll
        for (int ks = 0; ks < 4; ks++) {
            const int kb = (ks * 16 + tg * 2) * 2;     // byte offset of k pair
            uint32_t ahi[2][4], alo[2][4];
            #pragma unroll
            for (int mt = 0; mt < 2; mt++) {
                int r = (wm * 32 + mt * 16 + g) * ROWB + kb;
                ahi[mt][0] = *(const uint32_t*)(smem + SA_HI + r);
                ahi[mt][1] = *(const uint32_t*)(smem + SA_HI + r + 8 * ROWB);
                ahi[mt][2] = *(const uint32_t*)(smem + SA_HI + r + 16);
                ahi[mt][3] = *(const uint32_t*)(smem + SA_HI + r + 8 * ROWB + 16);
                alo[mt][0] = *(const uint32_t*)(smem + SA_LO + r);
                alo[mt][1] = *(const uint32_t*)(smem + SA_LO + r + 8 * ROWB);
                alo[mt][2] = *(const uint32_t*)(smem + SA_LO + r + 16);
                alo[mt][3] = *(const uint32_t*)(smem + SA_LO + r + 8 * ROWB + 16);
            }
            #pragma unroll
            for (int nt = 0; nt < 8; nt++) {
                int bofs = (wn * 64 + nt * 8 + g) * ROWB + kb;
                uint32_t bhi[2], blo[2];
                bhi[0] = *(const uint32_t*)(smem + SB_HI + bofs);
                bhi[1] = *(const uint32_t*)(smem + SB_HI + bofs + 16);
                blo[0] = *(const uint32_t*)(smem + SB_LO + bofs);
                blo[1] = *(const uint32_t*)(smem + SB_LO + bofs + 16);
                #pragma unroll
                for (int mt = 0; mt < 2; mt++) {
                    mma_bf16(acc[mt][nt], ahi[mt], bhi);
                    mma_bf16(acc[mt][nt], ahi[mt], blo);
                    mma_bf16(acc[mt][nt], alo[mt], bhi);
                }
            }
        }
        __syncthreads();   // single-buffered: protect smem before next fill
    }

    // ---- epilogue: degree-scaled biases + relu ----
    #pragma unroll
    for (int mt = 0; mt < 2; mt++) {
        int r0 = m0 + wm * 32 + mt * 16 + g;
        int r1 = r0 + 8;
        float dO0 = 0.f, dI0 = 0.f, dO1 = 0.f, dI1 = 0.f;
        if (r0 < NN) { dO0 = (float)g_deg_out[r0]; dI0 = (float)g_deg_in[r0]; }
        if (r1 < NN) { dO1 = (float)g_deg_out[r1]; dI1 = (float)g_deg_in[r1]; }
        #pragma unroll
        for (int nt = 0; nt < 8; nt++) {
            int ncol = wn * 64 + nt * 8 + tg * 2;
            float2 sbv = __ldg((const float2*)(Wsb + ncol));
            float2 wbv = __ldg((const float2*)(Wb  + ncol));
            float2 tbv = __ldg((const float2*)(Wtb + ncol));
            if (r0 < NN) {
                float v0 = acc[mt][nt][0] + sbv.x + dO0 * wbv.x + dI0 * tbv.x;
                float v1 = acc[mt][nt][1] + sbv.y + dO0 * wbv.y + dI0 * tbv.y;
                v0 = v0 > 0.f ? v0 : 0.f;
                v1 = v1 > 0.f ? v1 : 0.f;
                *(float2*)(out + (size_t)r0 * HH + ncol) = make_float2(v0, v1);
            }
            if (r1 < NN) {
                float v2 = acc[mt][nt][2] + sbv.x + dO1 * wbv.x + dI1 * tbv.x;
                float v3 = acc[mt][nt][3] + sbv.y + dO1 * wbv.y + dI1 * tbv.y;
                v2 = v2 > 0.f ? v2 : 0.f;
                v3 = v3 > 0.f ? v3 : 0.f;
                *(float2*)(out + (size_t)r1 * HH + ncol) = make_float2(v2, v3);
            }
        }
    }
}

// ---------------- launcher ----------------------------------------------------
extern "C" void kernel_launch(void* const* d_in, const int* in_sizes, int n_in,
                              void* d_out, int out_size) {
    const float* h_n  = (const float*)d_in[0];
    const int*   esrc = (const int*)  d_in[1];
    const int*   edst = (const int*)  d_in[2];
    const float* W_w  = (const float*)d_in[3];
    const float* W_b  = (const float*)d_in[4];
    const float* Ws_w = (const float*)d_in[5];
    const float* Ws_b = (const float*)d_in[6];
    const float* Wt_w = (const float*)d_in[7];
    const float* Wt_b = (const float*)d_in[8];
    float* out = (float*)d_out;

    cudaFuncSetAttribute(gemm_mma_kernel,
                         cudaFuncAttributeMaxDynamicSharedMemorySize, SM_TOT);

    prep_b_kernel<<<(128 * 384 + 255) / 256, 256>>>(W_w, Ws_w, Wt_w);
    zero_deg_kernel<<<(NN + 255) / 256, 256>>>();
    hist_kernel<<<(NE + 255) / 256, 256>>>(esrc, edst);
    scan1_kernel<<<dim3(SCAN_BLKS, 2), 1024>>>();
    scan2_kernel<<<2, 128>>>();
    scan3_kernel<<<dim3(SCAN_BLKS, 2), 1024>>>();
    build_kernel<<<(NE + 255) / 256, 256>>>(esrc, edst);
    agg_kernel<<<(NN * 32 + 255) / 256, 256>>>(h_n);
    gemm_mma_kernel<<<(NN + 127) / 128, 256, SM_TOT>>>(h_n, W_b, Ws_b, Wt_b, out);
}